// round 1
// baseline (speedup 1.0000x reference)
#include <cuda_runtime.h>
#include <math.h>

#define NB    8
#define LQ    1000
#define DM    256
#define NH    8
#define DH    32
#define NLV   4
#define NPT   4
#define LEN_IN 21760
#define DFFN  1024
#define NQ    (NB*LQ)    /* 8000 */

// ---------------- scratch (device globals; no allocation allowed) ----------
__device__ float g_qk[NQ*DM];
__device__ float g_q[NQ*DM];
__device__ float g_k[NQ*DM];
__device__ float g_v[NQ*DM];
__device__ float g_att[NQ*DM];     // attn-core out / deform-core out
__device__ float g_proj[NQ*DM];    // sa / ca projection out
__device__ float g_tgt2[NQ*DM];
__device__ float g_query[NQ*DM];
__device__ float g_off[NQ*DM];
__device__ float g_aw[NQ*128];
__device__ float g_ffn[NQ*DFFN];
__device__ float g_value[(size_t)NB*LEN_IN*DM];

// ---------------- elementwise add (qk = tgt + pos) -------------------------
__global__ void add_kernel(const float* __restrict__ a, const float* __restrict__ b,
                           float* __restrict__ o, int n4) {
    int i = blockIdx.x * blockDim.x + threadIdx.x;
    if (i < n4) {
        float4 x = ((const float4*)a)[i];
        float4 y = ((const float4*)b)[i];
        x.x += y.x; x.y += y.y; x.z += y.z; x.w += y.w;
        ((float4*)o)[i] = x;
    }
}

// ---------------- SGEMM: C[M,N] = A[M,K] @ B[N,K]^T + bias, opt. ReLU ------
// BM=BN=128, BK=8, 256 threads, 8x8 per thread.
template<bool RELU>
__global__ __launch_bounds__(256)
void sgemm_bias(const float* __restrict__ A, const float* __restrict__ B,
                const float* __restrict__ bias, float* __restrict__ C,
                int M, int N, int K) {
    __shared__ float As[8][128];
    __shared__ float Bs[8][128];
    const int tid = threadIdx.x;
    const int tx = tid & 15, ty = tid >> 4;
    const int rowBase = blockIdx.y * 128;
    const int colBase = blockIdx.x * 128;
    const int lRow = tid >> 1;
    const int lC4  = (tid & 1) * 4;

    float acc[8][8];
    #pragma unroll
    for (int i = 0; i < 8; i++)
        #pragma unroll
        for (int j = 0; j < 8; j++) acc[i][j] = 0.f;

    for (int k0 = 0; k0 < K; k0 += 8) {
        int gr = rowBase + lRow;
        float4 av = make_float4(0.f, 0.f, 0.f, 0.f);
        if (gr < M) av = *(const float4*)(A + (size_t)gr * K + k0 + lC4);
        As[lC4 + 0][lRow] = av.x;
        As[lC4 + 1][lRow] = av.y;
        As[lC4 + 2][lRow] = av.z;
        As[lC4 + 3][lRow] = av.w;

        int gc = colBase + lRow;
        float4 bv = make_float4(0.f, 0.f, 0.f, 0.f);
        if (gc < N) bv = *(const float4*)(B + (size_t)gc * K + k0 + lC4);
        Bs[lC4 + 0][lRow] = bv.x;
        Bs[lC4 + 1][lRow] = bv.y;
        Bs[lC4 + 2][lRow] = bv.z;
        Bs[lC4 + 3][lRow] = bv.w;
        __syncthreads();

        #pragma unroll
        for (int kk = 0; kk < 8; kk++) {
            float ar[8], br[8];
            *(float4*)(ar + 0) = *(const float4*)&As[kk][ty * 8 + 0];
            *(float4*)(ar + 4) = *(const float4*)&As[kk][ty * 8 + 4];
            *(float4*)(br + 0) = *(const float4*)&Bs[kk][tx * 8 + 0];
            *(float4*)(br + 4) = *(const float4*)&Bs[kk][tx * 8 + 4];
            #pragma unroll
            for (int i = 0; i < 8; i++)
                #pragma unroll
                for (int j = 0; j < 8; j++)
                    acc[i][j] = fmaf(ar[i], br[j], acc[i][j]);
        }
        __syncthreads();
    }

    float bs[8];
    #pragma unroll
    for (int j = 0; j < 8; j++) bs[j] = bias[colBase + tx * 8 + j];

    #pragma unroll
    for (int i = 0; i < 8; i++) {
        int r = rowBase + ty * 8 + i;
        if (r < M) {
            #pragma unroll
            for (int j = 0; j < 8; j++) {
                float v = acc[i][j] + bs[j];
                if (RELU) v = fmaxf(v, 0.f);
                C[(size_t)r * N + colBase + tx * 8 + j] = v;
            }
        }
    }
}

// ---------------- flash self-attention (per (b,h), 1 thread = 1 query) -----
__global__ __launch_bounds__(128)
void attn_kernel(const float* __restrict__ q, const float* __restrict__ k,
                 const float* __restrict__ v, float* __restrict__ out) {
    const int bh = blockIdx.y;
    const int b = bh / NH, h = bh % NH;
    const int qi = blockIdx.x * 128 + threadIdx.x;
    const bool valid = qi < LQ;
    const float scale = 0.1767766952966369f; // 1/sqrt(32)

    const float* qb = q + (size_t)b * LQ * DM + h * DH;
    const float* kb = k + (size_t)b * LQ * DM + h * DH;
    const float* vb = v + (size_t)b * LQ * DM + h * DH;

    __shared__ float ks[32][32];
    __shared__ float vs[32][32];

    float qr[32];
    if (valid) {
        #pragma unroll
        for (int c = 0; c < 8; c++) {
            float4 t = *(const float4*)(qb + (size_t)qi * DM + c * 4);
            qr[c * 4 + 0] = t.x; qr[c * 4 + 1] = t.y;
            qr[c * 4 + 2] = t.z; qr[c * 4 + 3] = t.w;
        }
    }

    float m = -1e30f, l = 0.f;
    float accv[32];
    #pragma unroll
    for (int d = 0; d < 32; d++) accv[d] = 0.f;

    for (int kt = 0; kt < LQ; kt += 32) {
        // cooperative load of 32 keys / values (32x32 floats each)
        #pragma unroll
        for (int i = threadIdx.x; i < 256; i += 128) {
            int r = i >> 3, c4 = (i & 7) * 4;
            int kr = kt + r;
            float4 kv = make_float4(0.f, 0.f, 0.f, 0.f), vv = kv;
            if (kr < LQ) {
                kv = *(const float4*)(kb + (size_t)kr * DM + c4);
                vv = *(const float4*)(vb + (size_t)kr * DM + c4);
            }
            *(float4*)&ks[r][c4] = kv;
            *(float4*)&vs[r][c4] = vv;
        }
        __syncthreads();

        if (valid) {
            int nk = LQ - kt; if (nk > 32) nk = 32;
            float s[32];
            float tmax = -1e30f;
            #pragma unroll
            for (int j = 0; j < 32; j++) {
                if (j < nk) {
                    const float4* kr4 = (const float4*)ks[j];
                    float dot = 0.f;
                    #pragma unroll
                    for (int c = 0; c < 8; c++) {
                        float4 kk = kr4[c];
                        dot = fmaf(qr[c*4+0], kk.x, dot);
                        dot = fmaf(qr[c*4+1], kk.y, dot);
                        dot = fmaf(qr[c*4+2], kk.z, dot);
                        dot = fmaf(qr[c*4+3], kk.w, dot);
                    }
                    s[j] = dot * scale;
                    tmax = fmaxf(tmax, s[j]);
                } else s[j] = -1e30f;
            }
            float mnew = fmaxf(m, tmax);
            float corr = __expf(m - mnew);
            l *= corr;
            #pragma unroll
            for (int d = 0; d < 32; d++) accv[d] *= corr;
            #pragma unroll
            for (int j = 0; j < 32; j++) {
                float p = __expf(s[j] - mnew);
                l += p;
                const float4* vr4 = (const float4*)vs[j];
                #pragma unroll
                for (int c = 0; c < 8; c++) {
                    float4 vv = vr4[c];
                    accv[c*4+0] = fmaf(p, vv.x, accv[c*4+0]);
                    accv[c*4+1] = fmaf(p, vv.y, accv[c*4+1]);
                    accv[c*4+2] = fmaf(p, vv.z, accv[c*4+2]);
                    accv[c*4+3] = fmaf(p, vv.w, accv[c*4+3]);
                }
            }
            m = mnew;
        }
        __syncthreads();
    }

    if (valid) {
        float inv = 1.f / l;
        float* ob = out + ((size_t)b * LQ + qi) * DM + h * DH;
        #pragma unroll
        for (int d = 0; d < 32; d++) ob[d] = accv[d] * inv;
    }
}

// ---------------- LayerNorm(x + res), optional (out + pos) second write ----
__global__ __launch_bounds__(256)
void ln_kernel(const float* __restrict__ x, const float* __restrict__ res,
               const float* __restrict__ g, const float* __restrict__ bta,
               float* __restrict__ out,
               const float* __restrict__ pos, float* __restrict__ outq) {
    __shared__ float red[8];
    const int row = blockIdx.x, t = threadIdx.x;
    const size_t idx = (size_t)row * DM + t;
    float v = x[idx] + res[idx];

    float s = v;
    #pragma unroll
    for (int o = 16; o; o >>= 1) s += __shfl_xor_sync(0xffffffffu, s, o);
    if ((t & 31) == 0) red[t >> 5] = s;
    __syncthreads();
    float mean = 0.f;
    #pragma unroll
    for (int i = 0; i < 8; i++) mean += red[i];
    mean *= (1.f / DM);
    __syncthreads();

    float d = v - mean;
    float s2 = d * d;
    #pragma unroll
    for (int o = 16; o; o >>= 1) s2 += __shfl_xor_sync(0xffffffffu, s2, o);
    if ((t & 31) == 0) red[t >> 5] = s2;
    __syncthreads();
    float var = 0.f;
    #pragma unroll
    for (int i = 0; i < 8; i++) var += red[i];
    var *= (1.f / DM);

    float o = d * rsqrtf(var + 1e-5f) * g[t] + bta[t];
    out[idx] = o;
    if (outq) outq[idx] = o + pos[idx];
}

// ---------------- attention-weight softmax over NL*NP=16 -------------------
__global__ void awsm_kernel(float* __restrict__ aw) {
    int i = blockIdx.x * blockDim.x + threadIdx.x;
    if (i >= NQ * NH) return;
    float* p = aw + (size_t)(i / NH) * 128 + (i % NH) * 16;
    float mx = -1e30f;
    #pragma unroll
    for (int j = 0; j < 16; j++) mx = fmaxf(mx, p[j]);
    float sm = 0.f, e[16];
    #pragma unroll
    for (int j = 0; j < 16; j++) { e[j] = __expf(p[j] - mx); sm += e[j]; }
    float inv = 1.f / sm;
    #pragma unroll
    for (int j = 0; j < 16; j++) p[j] = e[j] * inv;
}

// ---------------- MS-deformable sampling core ------------------------------
// grid: NQ blocks; block (32 = channel lane, 8 = head)
__global__ __launch_bounds__(256)
void deform_kernel(const float* __restrict__ value, const float* __restrict__ off,
                   const float* __restrict__ aw, const float* __restrict__ ref,
                   float* __restrict__ out) {
    const int qidx = blockIdx.x;           // 0..NQ-1
    const int b = qidx / LQ, q = qidx % LQ;
    const int h = threadIdx.y, d = threadIdx.x;

    const int   starts[4] = {0, 16384, 20480, 21504};
    const int   Wi[4]     = {128, 64, 32, 16};

    const float* vb = value + (size_t)b * LEN_IN * DM + h * DH + d;
    const size_t oq = (size_t)qidx;
    float acc = 0.f;

    #pragma unroll
    for (int lvl = 0; lvl < NLV; lvl++) {
        const float W = (float)Wi[lvl];
        const int   Wl = Wi[lvl];
        const int   st = starts[lvl];
        const float rx = ref[(oq * NLV + lvl) * 2 + 0];
        const float ry = ref[(oq * NLV + lvl) * 2 + 1];
        #pragma unroll
        for (int p = 0; p < NPT; p++) {
            const int oidx = ((h * NLV + lvl) * NPT + p) * 2;
            const float ox = off[oq * DM + oidx + 0];
            const float oy = off[oq * DM + oidx + 1];
            const float a  = aw[oq * 128 + h * 16 + lvl * 4 + p];
            const float x = (rx + ox / W) * W - 0.5f;
            const float y = (ry + oy / W) * W - 0.5f;
            const float x0f = floorf(x), y0f = floorf(y);
            const float lx = x - x0f, ly = y - y0f;
            const int x0 = (int)x0f, y0 = (int)y0f;

            const float w00 = (1.f - ly) * (1.f - lx);
            const float w01 = (1.f - ly) * lx;
            const float w10 = ly * (1.f - lx);
            const float w11 = ly * lx;

            const bool xv0 = (x0 >= 0) & (x0 < Wl);
            const bool xv1 = (x0 + 1 >= 0) & (x0 + 1 < Wl);
            const bool yv0 = (y0 >= 0) & (y0 < Wl);
            const bool yv1 = (y0 + 1 >= 0) & (y0 + 1 < Wl);

            if (yv0 & xv0) acc = fmaf(a * w00, vb[(size_t)(st + y0 * Wl + x0) * DM], acc);
            if (yv0 & xv1) acc = fmaf(a * w01, vb[(size_t)(st + y0 * Wl + x0 + 1) * DM], acc);
            if (yv1 & xv0) acc = fmaf(a * w10, vb[(size_t)(st + (y0 + 1) * Wl + x0) * DM], acc);
            if (yv1 & xv1) acc = fmaf(a * w11, vb[(size_t)(st + (y0 + 1) * Wl + x0 + 1) * DM], acc);
        }
    }
    out[oq * DM + h * DH + d] = acc;
}

// ---------------- host-side orchestration ----------------------------------
static inline void gemm(const float* A, const float* B, const float* bias, float* C,
                        int M, int N, int K, bool relu) {
    dim3 grid(N / 128, (M + 127) / 128);
    if (relu) sgemm_bias<true><<<grid, 256>>>(A, B, bias, C, M, N, K);
    else      sgemm_bias<false><<<grid, 256>>>(A, B, bias, C, M, N, K);
}

extern "C" void kernel_launch(void* const* d_in, const int* in_sizes, int n_in,
                              void* d_out, int out_size) {
    (void)in_sizes; (void)n_in; (void)out_size;
    const float* tgt       = (const float*)d_in[0];
    const float* query_pos = (const float*)d_in[1];
    const float* refpts    = (const float*)d_in[2];
    const float* src       = (const float*)d_in[3];
    // d_in[4] spatial_shapes, d_in[5] level_start_index: compile-time constants
    const float* sa_in_w   = (const float*)d_in[6];
    const float* sa_in_b   = (const float*)d_in[7];
    const float* sa_out_w  = (const float*)d_in[8];
    const float* sa_out_b  = (const float*)d_in[9];
    const float* norm2_g   = (const float*)d_in[10];
    const float* norm2_b   = (const float*)d_in[11];
    const float* off_w     = (const float*)d_in[12];
    const float* off_b     = (const float*)d_in[13];
    const float* aw_w      = (const float*)d_in[14];
    const float* aw_b      = (const float*)d_in[15];
    const float* val_w     = (const float*)d_in[16];
    const float* val_b     = (const float*)d_in[17];
    const float* outp_w    = (const float*)d_in[18];
    const float* outp_b    = (const float*)d_in[19];
    const float* norm1_g   = (const float*)d_in[20];
    const float* norm1_b   = (const float*)d_in[21];
    const float* ffn_w1    = (const float*)d_in[22];
    const float* ffn_b1    = (const float*)d_in[23];
    const float* ffn_w2    = (const float*)d_in[24];
    const float* ffn_b2    = (const float*)d_in[25];
    const float* norm3_g   = (const float*)d_in[26];
    const float* norm3_b   = (const float*)d_in[27];
    float* out = (float*)d_out;

    void* p;
    #define SYM(name) cudaGetSymbolAddress(&p, name); float* name##_p = (float*)p;
    SYM(g_qk)  SYM(g_q)  SYM(g_k)  SYM(g_v)  SYM(g_att) SYM(g_proj)
    SYM(g_tgt2) SYM(g_query) SYM(g_off) SYM(g_aw) SYM(g_ffn) SYM(g_value)
    #undef SYM

    const int n4 = NQ * DM / 4;
    // 1) qk = tgt + pos
    add_kernel<<<(n4 + 255) / 256, 256>>>(tgt, query_pos, g_qk_p, n4);
    // 2-4) in-proj
    gemm(g_qk_p, sa_in_w,            sa_in_b,            g_q_p, NQ, DM, DM, false);
    gemm(g_qk_p, sa_in_w + DM * DM,  sa_in_b + DM,       g_k_p, NQ, DM, DM, false);
    gemm(tgt,    sa_in_w + 2*DM*DM,  sa_in_b + 2*DM,     g_v_p, NQ, DM, DM, false);
    // 5) flash attention
    attn_kernel<<<dim3((LQ + 127) / 128, NB * NH), 128>>>(g_q_p, g_k_p, g_v_p, g_att_p);
    // 6) out proj
    gemm(g_att_p, sa_out_w, sa_out_b, g_proj_p, NQ, DM, DM, false);
    // 7) tgt2 = LN(tgt + sa); query = tgt2 + pos
    ln_kernel<<<NQ, DM>>>(tgt, g_proj_p, norm2_g, norm2_b, g_tgt2_p, query_pos, g_query_p);
    // 8) value projection (big GEMM)
    gemm(src, val_w, val_b, g_value_p, NB * LEN_IN, DM, DM, false);
    // 9-10) offsets & attention weights
    gemm(g_query_p, off_w, off_b, g_off_p, NQ, DM, DM, false);
    gemm(g_query_p, aw_w,  aw_b,  g_aw_p,  NQ, 128, DM, false);
    // 11) softmax over 16
    awsm_kernel<<<(NQ * NH + 255) / 256, 256>>>(g_aw_p);
    // 12) deformable sampling
    deform_kernel<<<NQ, dim3(32, 8)>>>(g_value_p, g_off_p, g_aw_p, refpts, g_att_p);
    // 13) output projection
    gemm(g_att_p, outp_w, outp_b, g_proj_p, NQ, DM, DM, false);
    // 14) tgt3 = LN(tgt2 + ca)   (reuse g_qk as tgt3)
    ln_kernel<<<NQ, DM>>>(g_tgt2_p, g_proj_p, norm1_g, norm1_b, g_qk_p, nullptr, nullptr);
    // 15-16) FFN
    gemm(g_qk_p, ffn_w1, ffn_b1, g_ffn_p, NQ, DFFN, DM, true);
    gemm(g_ffn_p, ffn_w2, ffn_b2, g_proj_p, NQ, DM, DFFN, false);
    // 17) out = LN(tgt3 + ff)
    ln_kernel<<<NQ, DM>>>(g_qk_p, g_proj_p, norm3_g, norm3_b, out, nullptr, nullptr);
}

// round 3
// speedup vs baseline: 1.6908x; 1.6908x over previous
#include <cuda_runtime.h>
#include <cuda_bf16.h>
#include <math.h>
#include <stdint.h>

#define NB    8
#define LQ    1000
#define DM    256
#define NH    8
#define DH    32
#define NLV   4
#define NPT   4
#define LEN_IN 21760
#define DFFN  1024
#define NQ    (NB*LQ)    /* 8000 */

// ---------------- scratch (device globals; no allocation allowed) ----------
__device__ float g_qk[NQ*DM];
__device__ float g_q[NQ*DM];
__device__ float g_k[NQ*DM];
__device__ float g_v[NQ*DM];
__device__ float g_att[NQ*DM];
__device__ float g_proj[NQ*DM];
__device__ float g_tgt2[NQ*DM];
__device__ float g_query[NQ*DM];
__device__ float g_off[NQ*DM];
__device__ float g_aw[NQ*128];
__device__ float g_ffn[NQ*DFFN];
__device__ float g_value[(size_t)NB*LEN_IN*DM];

// =================== mma.sync helpers ======================================
__device__ __forceinline__ uint32_t smem_u32(const void* p) {
    uint32_t a;
    asm("{ .reg .u64 t; cvta.to.shared.u64 t, %1; cvt.u32.u64 %0, t; }" : "=r"(a) : "l"(p));
    return a;
}
__device__ __forceinline__ void ldmx4(uint32_t addr, uint32_t* r) {
    asm volatile("ldmatrix.sync.aligned.m8n8.x4.shared.b16 {%0,%1,%2,%3}, [%4];"
                 : "=r"(r[0]), "=r"(r[1]), "=r"(r[2]), "=r"(r[3]) : "r"(addr));
}
__device__ __forceinline__ void mma16816(float* d, const uint32_t* a, uint32_t b0, uint32_t b1) {
    asm volatile("mma.sync.aligned.m16n8k16.row.col.f32.bf16.bf16.f32 "
                 "{%0,%1,%2,%3}, {%4,%5,%6,%7}, {%8,%9}, {%0,%1,%2,%3};"
                 : "+f"(d[0]), "+f"(d[1]), "+f"(d[2]), "+f"(d[3])
                 : "r"(a[0]), "r"(a[1]), "r"(a[2]), "r"(a[3]), "r"(b0), "r"(b1));
}

// =================== tensor-core GEMM: C[M,N]=A[M,K]@B[N,K]^T + bias =======
// 128x128 tile, BK=32. 8 warps: warp tile 32(M)x64(N). bf16 hi/lo split,
// 3 products (AhBh + AhBl + AlBh) for near-fp32 accuracy.
#define TCSTR 40   /* smem row stride in bf16 elems (80 bytes, conflict-free) */

template<bool RELU>
__global__ __launch_bounds__(256)
void tc_gemm(const float* __restrict__ A, const float* __restrict__ B,
             const float* __restrict__ bias, float* __restrict__ C,
             int M, int N, int K) {
    __shared__ __nv_bfloat16 sAh[128*TCSTR];
    __shared__ __nv_bfloat16 sAl[128*TCSTR];
    __shared__ __nv_bfloat16 sBh[128*TCSTR];
    __shared__ __nv_bfloat16 sBl[128*TCSTR];

    const int tid  = threadIdx.x;
    const int lane = tid & 31;
    const int wid  = tid >> 5;
    const int warpM = wid & 3;            // 0..3  -> rows  warpM*32
    const int warpN = wid >> 2;           // 0..1  -> cols  warpN*64
    const int rowBase = blockIdx.y * 128;
    const int colBase = blockIdx.x * 128;

    const uint32_t uAh = smem_u32(sAh), uAl = smem_u32(sAl);
    const uint32_t uBh = smem_u32(sBh), uBl = smem_u32(sBl);

    float acc[2][8][4];
    #pragma unroll
    for (int mt = 0; mt < 2; mt++)
        #pragma unroll
        for (int nt = 0; nt < 8; nt++)
            #pragma unroll
            for (int i = 0; i < 4; i++) acc[mt][nt][i] = 0.f;

    // gmem load indices: 256 threads load 32 rows x 8 float4 per pass
    const int ldRow = tid >> 3;           // 0..31
    const int ldC4  = (tid & 7) * 4;      // 0,4,..,28

    // ldmatrix source addresses (element offsets computed per k-step)
    const int aRow = (lane & 15);
    const int aColOff = (lane >> 4) * 8;
    const int bRow = (lane & 7) + ((lane >> 4) & 1) * 8;
    const int bColOff = ((lane >> 3) & 1) * 8;

    for (int k0 = 0; k0 < K; k0 += 32) {
        if (k0) __syncthreads();
        // ---- load + split fp32 -> bf16 hi/lo into smem --------------------
        #pragma unroll
        for (int p = 0; p < 4; p++) {
            const int r = p * 32 + ldRow;
            // A
            {
                const int gr = rowBase + r;
                float4 v = make_float4(0.f,0.f,0.f,0.f);
                if (gr < M) v = *(const float4*)(A + (size_t)gr * K + k0 + ldC4);
                __nv_bfloat16 h0=__float2bfloat16(v.x), h1=__float2bfloat16(v.y);
                __nv_bfloat16 h2=__float2bfloat16(v.z), h3=__float2bfloat16(v.w);
                __nv_bfloat16 l0=__float2bfloat16(v.x-__bfloat162float(h0));
                __nv_bfloat16 l1=__float2bfloat16(v.y-__bfloat162float(h1));
                __nv_bfloat16 l2=__float2bfloat16(v.z-__bfloat162float(h2));
                __nv_bfloat16 l3=__float2bfloat16(v.w-__bfloat162float(h3));
                __nv_bfloat162* dh = (__nv_bfloat162*)&sAh[r*TCSTR + ldC4];
                __nv_bfloat162* dl = (__nv_bfloat162*)&sAl[r*TCSTR + ldC4];
                dh[0] = __nv_bfloat162(h0,h1); dh[1] = __nv_bfloat162(h2,h3);
                dl[0] = __nv_bfloat162(l0,l1); dl[1] = __nv_bfloat162(l2,l3);
            }
            // B
            {
                const int gc = colBase + r;
                float4 v = make_float4(0.f,0.f,0.f,0.f);
                if (gc < N) v = *(const float4*)(B + (size_t)gc * K + k0 + ldC4);
                __nv_bfloat16 h0=__float2bfloat16(v.x), h1=__float2bfloat16(v.y);
                __nv_bfloat16 h2=__float2bfloat16(v.z), h3=__float2bfloat16(v.w);
                __nv_bfloat16 l0=__float2bfloat16(v.x-__bfloat162float(h0));
                __nv_bfloat16 l1=__float2bfloat16(v.y-__bfloat162float(h1));
                __nv_bfloat16 l2=__float2bfloat16(v.z-__bfloat162float(h2));
                __nv_bfloat16 l3=__float2bfloat16(v.w-__bfloat162float(h3));
                __nv_bfloat162* dh = (__nv_bfloat162*)&sBh[r*TCSTR + ldC4];
                __nv_bfloat162* dl = (__nv_bfloat162*)&sBl[r*TCSTR + ldC4];
                dh[0] = __nv_bfloat162(h0,h1); dh[1] = __nv_bfloat162(h2,h3);
                dl[0] = __nv_bfloat162(l0,l1); dl[1] = __nv_bfloat162(l2,l3);
            }
        }
        __syncthreads();

        // ---- 2 k-steps of 16 ---------------------------------------------
        #pragma unroll
        for (int ks = 0; ks < 32; ks += 16) {
            uint32_t ah[2][4], al[2][4];
            #pragma unroll
            for (int mt = 0; mt < 2; mt++) {
                const int r0 = warpM * 32 + mt * 16;
                uint32_t off = (uint32_t)((r0 + aRow) * TCSTR + ks + aColOff) * 2;
                ldmx4(uAh + off, ah[mt]);
                ldmx4(uAl + off, al[mt]);
            }
            uint32_t bh[4][4], bl[4][4];
            #pragma unroll
            for (int nb = 0; nb < 4; nb++) {
                const int n0 = warpN * 64 + nb * 16;
                uint32_t off = (uint32_t)((n0 + bRow) * TCSTR + ks + bColOff) * 2;
                ldmx4(uBh + off, bh[nb]);
                ldmx4(uBl + off, bl[nb]);
            }
            #pragma unroll
            for (int mt = 0; mt < 2; mt++) {
                #pragma unroll
                for (int nt = 0; nt < 8; nt++) {
                    const int nb = nt >> 1, hi = (nt & 1) * 2;
                    mma16816(acc[mt][nt], ah[mt], bh[nb][hi], bh[nb][hi+1]);
                    mma16816(acc[mt][nt], ah[mt], bl[nb][hi], bl[nb][hi+1]);
                    mma16816(acc[mt][nt], al[mt], bh[nb][hi], bh[nb][hi+1]);
                }
            }
        }
    }

    // ---- epilogue ---------------------------------------------------------
    #pragma unroll
    for (int mt = 0; mt < 2; mt++) {
        #pragma unroll
        for (int half = 0; half < 2; half++) {
            const int row = rowBase + warpM * 32 + mt * 16 + (lane >> 2) + half * 8;
            if (row < M) {
                #pragma unroll
                for (int nt = 0; nt < 8; nt++) {
                    const int col = colBase + warpN * 64 + nt * 8 + (lane & 3) * 2;
                    float2 o;
                    o.x = acc[mt][nt][half*2+0] + bias[col];
                    o.y = acc[mt][nt][half*2+1] + bias[col+1];
                    if (RELU) { o.x = fmaxf(o.x, 0.f); o.y = fmaxf(o.y, 0.f); }
                    *(float2*)(C + (size_t)row * N + col) = o;
                }
            }
        }
    }
}

// ---------------- elementwise add (qk = tgt + pos) -------------------------
__global__ void add_kernel(const float* __restrict__ a, const float* __restrict__ b,
                           float* __restrict__ o, int n4) {
    int i = blockIdx.x * blockDim.x + threadIdx.x;
    if (i < n4) {
        float4 x = ((const float4*)a)[i];
        float4 y = ((const float4*)b)[i];
        x.x += y.x; x.y += y.y; x.z += y.z; x.w += y.w;
        ((float4*)o)[i] = x;
    }
}

// ---------------- flash self-attention (per (b,h), 1 thread = 1 query) -----
__global__ __launch_bounds__(128)
void attn_kernel(const float* __restrict__ q, const float* __restrict__ k,
                 const float* __restrict__ v, float* __restrict__ out) {
    const int bh = blockIdx.y;
    const int b = bh / NH, h = bh % NH;
    const int qi = blockIdx.x * 128 + threadIdx.x;
    const bool valid = qi < LQ;
    const float scale = 0.1767766952966369f;

    const float* qb = q + (size_t)b * LQ * DM + h * DH;
    const float* kb = k + (size_t)b * LQ * DM + h * DH;
    const float* vb = v + (size_t)b * LQ * DM + h * DH;

    __shared__ float ks[32][32];
    __shared__ float vs[32][32];

    float qr[32];
    if (valid) {
        #pragma unroll
        for (int c = 0; c < 8; c++) {
            float4 t = *(const float4*)(qb + (size_t)qi * DM + c * 4);
            qr[c * 4 + 0] = t.x; qr[c * 4 + 1] = t.y;
            qr[c * 4 + 2] = t.z; qr[c * 4 + 3] = t.w;
        }
    }

    float m = -1e30f, l = 0.f;
    float accv[32];
    #pragma unroll
    for (int d = 0; d < 32; d++) accv[d] = 0.f;

    for (int kt = 0; kt < LQ; kt += 32) {
        #pragma unroll
        for (int i = threadIdx.x; i < 256; i += 128) {
            int r = i >> 3, c4 = (i & 7) * 4;
            int kr = kt + r;
            float4 kv = make_float4(0.f, 0.f, 0.f, 0.f), vv = kv;
            if (kr < LQ) {
                kv = *(const float4*)(kb + (size_t)kr * DM + c4);
                vv = *(const float4*)(vb + (size_t)kr * DM + c4);
            }
            *(float4*)&ks[r][c4] = kv;
            *(float4*)&vs[r][c4] = vv;
        }
        __syncthreads();

        if (valid) {
            int nk = LQ - kt; if (nk > 32) nk = 32;
            float s[32];
            float tmax = -1e30f;
            #pragma unroll
            for (int j = 0; j < 32; j++) {
                if (j < nk) {
                    const float4* kr4 = (const float4*)ks[j];
                    float dot = 0.f;
                    #pragma unroll
                    for (int c = 0; c < 8; c++) {
                        float4 kk = kr4[c];
                        dot = fmaf(qr[c*4+0], kk.x, dot);
                        dot = fmaf(qr[c*4+1], kk.y, dot);
                        dot = fmaf(qr[c*4+2], kk.z, dot);
                        dot = fmaf(qr[c*4+3], kk.w, dot);
                    }
                    s[j] = dot * scale;
                    tmax = fmaxf(tmax, s[j]);
                } else s[j] = -1e30f;
            }
            float mnew = fmaxf(m, tmax);
            float corr = __expf(m - mnew);
            l *= corr;
            #pragma unroll
            for (int d = 0; d < 32; d++) accv[d] *= corr;
            #pragma unroll
            for (int j = 0; j < 32; j++) {
                float p = __expf(s[j] - mnew);
                l += p;
                const float4* vr4 = (const float4*)vs[j];
                #pragma unroll
                for (int c = 0; c < 8; c++) {
                    float4 vv = vr4[c];
                    accv[c*4+0] = fmaf(p, vv.x, accv[c*4+0]);
                    accv[c*4+1] = fmaf(p, vv.y, accv[c*4+1]);
                    accv[c*4+2] = fmaf(p, vv.z, accv[c*4+2]);
                    accv[c*4+3] = fmaf(p, vv.w, accv[c*4+3]);
                }
            }
            m = mnew;
        }
        __syncthreads();
    }

    if (valid) {
        float inv = 1.f / l;
        float* ob = out + ((size_t)b * LQ + qi) * DM + h * DH;
        #pragma unroll
        for (int d = 0; d < 32; d++) ob[d] = accv[d] * inv;
    }
}

// ---------------- LayerNorm(x + res), optional (out + pos) second write ----
__global__ __launch_bounds__(256)
void ln_kernel(const float* __restrict__ x, const float* __restrict__ res,
               const float* __restrict__ g, const float* __restrict__ bta,
               float* __restrict__ out,
               const float* __restrict__ pos, float* __restrict__ outq) {
    __shared__ float red[8];
    const int row = blockIdx.x, t = threadIdx.x;
    const size_t idx = (size_t)row * DM + t;
    float v = x[idx] + res[idx];

    float s = v;
    #pragma unroll
    for (int o = 16; o; o >>= 1) s += __shfl_xor_sync(0xffffffffu, s, o);
    if ((t & 31) == 0) red[t >> 5] = s;
    __syncthreads();
    float mean = 0.f;
    #pragma unroll
    for (int i = 0; i < 8; i++) mean += red[i];
    mean *= (1.f / DM);
    __syncthreads();

    float d = v - mean;
    float s2 = d * d;
    #pragma unroll
    for (int o = 16; o; o >>= 1) s2 += __shfl_xor_sync(0xffffffffu, s2, o);
    if ((t & 31) == 0) red[t >> 5] = s2;
    __syncthreads();
    float var = 0.f;
    #pragma unroll
    for (int i = 0; i < 8; i++) var += red[i];
    var *= (1.f / DM);

    float o = d * rsqrtf(var + 1e-5f) * g[t] + bta[t];
    out[idx] = o;
    if (outq) outq[idx] = o + pos[idx];
}

// ---------------- attention-weight softmax over NL*NP=16 -------------------
__global__ void awsm_kernel(float* __restrict__ aw) {
    int i = blockIdx.x * blockDim.x + threadIdx.x;
    if (i >= NQ * NH) return;
    float* p = aw + (size_t)(i / NH) * 128 + (i % NH) * 16;
    float mx = -1e30f;
    #pragma unroll
    for (int j = 0; j < 16; j++) mx = fmaxf(mx, p[j]);
    float sm = 0.f, e[16];
    #pragma unroll
    for (int j = 0; j < 16; j++) { e[j] = __expf(p[j] - mx); sm += e[j]; }
    float inv = 1.f / sm;
    #pragma unroll
    for (int j = 0; j < 16; j++) p[j] = e[j] * inv;
}

// ---------------- MS-deformable sampling core ------------------------------
__global__ __launch_bounds__(256)
void deform_kernel(const float* __restrict__ value, const float* __restrict__ off,
                   const float* __restrict__ aw, const float* __restrict__ ref,
                   float* __restrict__ out) {
    const int qidx = blockIdx.x;
    const int b = qidx / LQ;
    const int h = threadIdx.y, d = threadIdx.x;

    const int   starts[4] = {0, 16384, 20480, 21504};
    const int   Wi[4]     = {128, 64, 32, 16};

    const float* vb = value + (size_t)b * LEN_IN * DM + h * DH + d;
    const size_t oq = (size_t)qidx;
    float acc = 0.f;

    #pragma unroll
    for (int lvl = 0; lvl < NLV; lvl++) {
        const float W = (float)Wi[lvl];
        const int   Wl = Wi[lvl];
        const int   st = starts[lvl];
        const float rx = ref[(oq * NLV + lvl) * 2 + 0];
        const float ry = ref[(oq * NLV + lvl) * 2 + 1];
        #pragma unroll
        for (int p = 0; p < NPT; p++) {
            const int oidx = ((h * NLV + lvl) * NPT + p) * 2;
            const float ox = off[oq * DM + oidx + 0];
            const float oy = off[oq * DM + oidx + 1];
            const float a  = aw[oq * 128 + h * 16 + lvl * 4 + p];
            const float x = (rx + ox / W) * W - 0.5f;
            const float y = (ry + oy / W) * W - 0.5f;
            const float x0f = floorf(x), y0f = floorf(y);
            const float lx = x - x0f, ly = y - y0f;
            const int x0 = (int)x0f, y0 = (int)y0f;

            const float w00 = (1.f - ly) * (1.f - lx);
            const float w01 = (1.f - ly) * lx;
            const float w10 = ly * (1.f - lx);
            const float w11 = ly * lx;

            const bool xv0 = (x0 >= 0) & (x0 < Wl);
            const bool xv1 = (x0 + 1 >= 0) & (x0 + 1 < Wl);
            const bool yv0 = (y0 >= 0) & (y0 < Wl);
            const bool yv1 = (y0 + 1 >= 0) & (y0 + 1 < Wl);

            if (yv0 & xv0) acc = fmaf(a * w00, vb[(size_t)(st + y0 * Wl + x0) * DM], acc);
            if (yv0 & xv1) acc = fmaf(a * w01, vb[(size_t)(st + y0 * Wl + x0 + 1) * DM], acc);
            if (yv1 & xv0) acc = fmaf(a * w10, vb[(size_t)(st + (y0 + 1) * Wl + x0) * DM], acc);
            if (yv1 & xv1) acc = fmaf(a * w11, vb[(size_t)(st + (y0 + 1) * Wl + x0 + 1) * DM], acc);
        }
    }
    out[oq * DM + h * DH + d] = acc;
}

// ---------------- host-side orchestration ----------------------------------
static inline void gemm(const float* A, const float* B, const float* bias, float* C,
                        int M, int N, int K, bool relu) {
    dim3 grid(N / 128, (M + 127) / 128);
    if (relu) tc_gemm<true><<<grid, 256>>>(A, B, bias, C, M, N, K);
    else      tc_gemm<false><<<grid, 256>>>(A, B, bias, C, M, N, K);
}

extern "C" void kernel_launch(void* const* d_in, const int* in_sizes, int n_in,
                              void* d_out, int out_size) {
    (void)in_sizes; (void)n_in; (void)out_size;
    const float* tgt       = (const float*)d_in[0];
    const float* query_pos = (const float*)d_in[1];
    const float* refpts    = (const float*)d_in[2];
    const float* src       = (const float*)d_in[3];
    const float* sa_in_w   = (const float*)d_in[6];
    const float* sa_in_b   = (const float*)d_in[7];
    const float* sa_out_w  = (const float*)d_in[8];
    const float* sa_out_b  = (const float*)d_in[9];
    const float* norm2_g   = (const float*)d_in[10];
    const float* norm2_b   = (const float*)d_in[11];
    const float* off_w     = (const float*)d_in[12];
    const float* off_b     = (const float*)d_in[13];
    const float* aw_w      = (const float*)d_in[14];
    const float* aw_b      = (const float*)d_in[15];
    const float* val_w     = (const float*)d_in[16];
    const float* val_b     = (const float*)d_in[17];
    const float* outp_w    = (const float*)d_in[18];
    const float* outp_b    = (const float*)d_in[19];
    const float* norm1_g   = (const float*)d_in[20];
    const float* norm1_b   = (const float*)d_in[21];
    const float* ffn_w1    = (const float*)d_in[22];
    const float* ffn_b1    = (const float*)d_in[23];
    const float* ffn_w2    = (const float*)d_in[24];
    const float* ffn_b2    = (const float*)d_in[25];
    const float* norm3_g   = (const float*)d_in[26];
    const float* norm3_b   = (const float*)d_in[27];
    float* out = (float*)d_out;

    void* p;
    #define SYM(name) cudaGetSymbolAddress(&p, name); float* name##_p = (float*)p;
    SYM(g_qk)  SYM(g_q)  SYM(g_k)  SYM(g_v)  SYM(g_att) SYM(g_proj)
    SYM(g_tgt2) SYM(g_query) SYM(g_off) SYM(g_aw) SYM(g_ffn) SYM(g_value)
    #undef SYM

    const int n4 = NQ * DM / 4;
    add_kernel<<<(n4 + 255) / 256, 256>>>(tgt, query_pos, g_qk_p, n4);
    gemm(g_qk_p, sa_in_w,            sa_in_b,            g_q_p, NQ, DM, DM, false);
    gemm(g_qk_p, sa_in_w + DM * DM,  sa_in_b + DM,       g_k_p, NQ, DM, DM, false);
    gemm(tgt,    sa_in_w + 2*DM*DM,  sa_in_b + 2*DM,     g_v_p, NQ, DM, DM, false);
    attn_kernel<<<dim3((LQ + 127) / 128, NB * NH), 128>>>(g_q_p, g_k_p, g_v_p, g_att_p);
    gemm(g_att_p, sa_out_w, sa_out_b, g_proj_p, NQ, DM, DM, false);
    ln_kernel<<<NQ, DM>>>(tgt, g_proj_p, norm2_g, norm2_b, g_tgt2_p, query_pos, g_query_p);
    gemm(src, val_w, val_b, g_value_p, NB * LEN_IN, DM, DM, false);
    gemm(g_query_p, off_w, off_b, g_off_p, NQ, DM, DM, false);
    gemm(g_query_p, aw_w,  aw_b,  g_aw_p,  NQ, 128, DM, false);
    awsm_kernel<<<(NQ * NH + 255) / 256, 256>>>(g_aw_p);
    deform_kernel<<<NQ, dim3(32, 8)>>>(g_value_p, g_off_p, g_aw_p, refpts, g_att_p);
    gemm(g_att_p, outp_w, outp_b, g_proj_p, NQ, DM, DM, false);
    ln_kernel<<<NQ, DM>>>(g_tgt2_p, g_proj_p, norm1_g, norm1_b, g_qk_p, nullptr, nullptr);
    gemm(g_qk_p, ffn_w1, ffn_b1, g_ffn_p, NQ, DFFN, DM, true);
    gemm(g_ffn_p, ffn_w2, ffn_b2, g_proj_p, NQ, DM, DFFN, false);
    ln_kernel<<<NQ, DM>>>(g_qk_p, g_proj_p, norm3_g, norm3_b, out, nullptr, nullptr);
}

// round 4
// speedup vs baseline: 1.7935x; 1.0607x over previous
#include <cuda_runtime.h>
#include <cuda_bf16.h>
#include <math.h>
#include <stdint.h>

#define NB    8
#define LQ    1000
#define DM    256
#define NH    8
#define DH    32
#define NLV   4
#define NPT   4
#define LEN_IN 21760
#define DFFN  1024
#define NQ    (NB*LQ)    /* 8000 */
#define NSRC  (NB*LEN_IN) /* 174080 */

// ---------------- fp32 scratch ---------------------------------------------
__device__ float g_q[NQ*DM];
__device__ float g_k[NQ*DM];
__device__ float g_v[NQ*DM];
__device__ float g_proj[NQ*DM];
__device__ float g_tgt2[NQ*DM];
__device__ float g_tgt3[NQ*DM];
__device__ float g_off[NQ*DM];
__device__ float g_aw[NQ*128];
__device__ float g_value[(size_t)NSRC*DM];

// ---------------- bf16 hi/lo split scratch ---------------------------------
__device__ __nv_bfloat16 g_qk_h[NQ*DM],   g_qk_l[NQ*DM];
__device__ __nv_bfloat16 g_tgt_h[NQ*DM],  g_tgt_l[NQ*DM];
__device__ __nv_bfloat16 g_att_h[NQ*DM],  g_att_l[NQ*DM];
__device__ __nv_bfloat16 g_query_h[NQ*DM],g_query_l[NQ*DM];
__device__ __nv_bfloat16 g_tgt3_h[NQ*DM], g_tgt3_l[NQ*DM];
__device__ __nv_bfloat16 g_ca_h[NQ*DM],   g_ca_l[NQ*DM];
__device__ __nv_bfloat16 g_ffn_h[NQ*DFFN],g_ffn_l[NQ*DFFN];
__device__ __nv_bfloat16 g_src_h[(size_t)NSRC*DM], g_src_l[(size_t)NSRC*DM];

#define WTOT 1015808
#define OFF_SAIN  0
#define OFF_SAOUT 196608
#define OFF_OFFW  262144
#define OFF_AWW   327680
#define OFF_VALW  360448
#define OFF_OUTPW 425984
#define OFF_FFN1  491520
#define OFF_FFN2  753664
__device__ __nv_bfloat16 g_wh[WTOT], g_wl[WTOT];

// =================== helpers ===============================================
__device__ __forceinline__ uint32_t smem_u32(const void* p) {
    uint32_t a;
    asm("{ .reg .u64 t; cvta.to.shared.u64 t, %1; cvt.u32.u64 %0, t; }" : "=r"(a) : "l"(p));
    return a;
}
__device__ __forceinline__ void ldmx4(uint32_t addr, uint32_t* r) {
    asm volatile("ldmatrix.sync.aligned.m8n8.x4.shared.b16 {%0,%1,%2,%3}, [%4];"
                 : "=r"(r[0]), "=r"(r[1]), "=r"(r[2]), "=r"(r[3]) : "r"(addr));
}
__device__ __forceinline__ void mma16816(float* d, const uint32_t* a, uint32_t b0, uint32_t b1) {
    asm volatile("mma.sync.aligned.m16n8k16.row.col.f32.bf16.bf16.f32 "
                 "{%0,%1,%2,%3}, {%4,%5,%6,%7}, {%8,%9}, {%0,%1,%2,%3};"
                 : "+f"(d[0]), "+f"(d[1]), "+f"(d[2]), "+f"(d[3])
                 : "r"(a[0]), "r"(a[1]), "r"(a[2]), "r"(a[3]), "r"(b0), "r"(b1));
}
__device__ __forceinline__ void cp16z(uint32_t dst, const void* src, bool v) {
    asm volatile("cp.async.cg.shared.global [%0], [%1], 16, %2;"
                 :: "r"(dst), "l"(src), "r"(v ? 16 : 0));
}
__device__ __forceinline__ void split2(float v, __nv_bfloat16& h, __nv_bfloat16& l) {
    h = __float2bfloat16(v);
    l = __float2bfloat16(v - __bfloat162float(h));
}

// =================== bf16-split tensor GEMM ================================
// C[M,N] = A[M,K] @ B[N,K]^T + bias.  A,B given as bf16 hi/lo pairs.
// 128x128 tile, BK=32, 8 warps (32x64 warp tile), 2-stage cp.async pipeline.
#define TCSTR 40                 /* smem row stride elems (80B) */
#define TILE_AH 0
#define TILE_AL 10240
#define TILE_BH 20480
#define TILE_BL 30720
#define STAGE_TOTAL 40960
#define TCG_SMEM (2*STAGE_TOTAL)

__device__ __forceinline__ void stage_load(
    uint32_t sb, const __nv_bfloat16* Ah, const __nv_bfloat16* Al,
    const __nv_bfloat16* Bh, const __nv_bfloat16* Bl,
    int M, int N, int K, int rowBase, int colBase, int k0, int ldR, int ldC) {
    int gr = rowBase + ldR; bool av = gr < M; if (!av) gr = 0;
    const char* pa  = (const char*)(Ah + (size_t)gr * K + k0) + ldC;
    const char* pal = (const char*)(Al + (size_t)gr * K + k0) + ldC;
    uint32_t da  = sb + TILE_AH + ldR * 80 + ldC;
    uint32_t dal = sb + TILE_AL + ldR * 80 + ldC;
    cp16z(da, pa, av);        cp16z(da + 16, pa + 16, av);
    cp16z(dal, pal, av);      cp16z(dal + 16, pal + 16, av);
    int gc = colBase + ldR; bool bv = gc < N; if (!bv) gc = 0;
    const char* pb  = (const char*)(Bh + (size_t)gc * K + k0) + ldC;
    const char* pbl = (const char*)(Bl + (size_t)gc * K + k0) + ldC;
    uint32_t db  = sb + TILE_BH + ldR * 80 + ldC;
    uint32_t dbl = sb + TILE_BL + ldR * 80 + ldC;
    cp16z(db, pb, bv);        cp16z(db + 16, pb + 16, bv);
    cp16z(dbl, pbl, bv);      cp16z(dbl + 16, pbl + 16, bv);
    asm volatile("cp.async.commit_group;" ::: "memory");
}

template<bool RELU, bool SPLITOUT>
__global__ __launch_bounds__(256)
void tc_gemm_bf(const __nv_bfloat16* __restrict__ Ah, const __nv_bfloat16* __restrict__ Al,
                const __nv_bfloat16* __restrict__ Bh, const __nv_bfloat16* __restrict__ Bl,
                const float* __restrict__ bias, float* __restrict__ Cf,
                __nv_bfloat16* __restrict__ Chi, __nv_bfloat16* __restrict__ Clo,
                int M, int N, int K) {
    extern __shared__ char smem[];
    const uint32_t sbase = smem_u32(smem);
    const int tid  = threadIdx.x;
    const int lane = tid & 31;
    const int wid  = tid >> 5;
    const int warpM = wid & 3;
    const int warpN = wid >> 2;
    const int rowBase = blockIdx.y * 128;
    const int colBase = blockIdx.x * 128;
    const int ldR = tid >> 1;
    const int ldC = (tid & 1) * 32;

    const int aRow = (lane & 15);
    const int aColOff = (lane >> 4) * 8;
    const int bRow = (lane & 7) + ((lane >> 4) & 1) * 8;
    const int bColOff = ((lane >> 3) & 1) * 8;

    float acc[2][8][4];
    #pragma unroll
    for (int mt = 0; mt < 2; mt++)
        #pragma unroll
        for (int nt = 0; nt < 8; nt++)
            #pragma unroll
            for (int i = 0; i < 4; i++) acc[mt][nt][i] = 0.f;

    const int KC = K >> 5;
    stage_load(sbase, Ah, Al, Bh, Bl, M, N, K, rowBase, colBase, 0, ldR, ldC);

    for (int c = 0; c < KC; c++) {
        if (c + 1 < KC) {
            stage_load(sbase + ((c + 1) & 1) * STAGE_TOTAL, Ah, Al, Bh, Bl,
                       M, N, K, rowBase, colBase, (c + 1) << 5, ldR, ldC);
            asm volatile("cp.async.wait_group 1;" ::: "memory");
        } else {
            asm volatile("cp.async.wait_group 0;" ::: "memory");
        }
        __syncthreads();

        const uint32_t sb = sbase + (c & 1) * STAGE_TOTAL;
        #pragma unroll
        for (int ks = 0; ks < 32; ks += 16) {
            uint32_t ah[2][4], al[2][4];
            #pragma unroll
            for (int mt = 0; mt < 2; mt++) {
                const int r0 = warpM * 32 + mt * 16;
                uint32_t off = (uint32_t)((r0 + aRow) * TCSTR + ks + aColOff) * 2;
                ldmx4(sb + TILE_AH + off, ah[mt]);
                ldmx4(sb + TILE_AL + off, al[mt]);
            }
            uint32_t bh[4][4], bl[4][4];
            #pragma unroll
            for (int nb = 0; nb < 4; nb++) {
                const int n0 = warpN * 64 + nb * 16;
                uint32_t off = (uint32_t)((n0 + bRow) * TCSTR + ks + bColOff) * 2;
                ldmx4(sb + TILE_BH + off, bh[nb]);
                ldmx4(sb + TILE_BL + off, bl[nb]);
            }
            #pragma unroll
            for (int mt = 0; mt < 2; mt++) {
                #pragma unroll
                for (int nt = 0; nt < 8; nt++) {
                    const int nb = nt >> 1, hi = (nt & 1) * 2;
                    mma16816(acc[mt][nt], ah[mt], bh[nb][hi], bh[nb][hi+1]);
                    mma16816(acc[mt][nt], ah[mt], bl[nb][hi], bl[nb][hi+1]);
                    mma16816(acc[mt][nt], al[mt], bh[nb][hi], bh[nb][hi+1]);
                }
            }
        }
        __syncthreads();
    }

    // ---- epilogue ---------------------------------------------------------
    #pragma unroll
    for (int mt = 0; mt < 2; mt++) {
        #pragma unroll
        for (int half = 0; half < 2; half++) {
            const int row = rowBase + warpM * 32 + mt * 16 + (lane >> 2) + half * 8;
            if (row < M) {
                #pragma unroll
                for (int nt = 0; nt < 8; nt++) {
                    const int col = colBase + warpN * 64 + nt * 8 + (lane & 3) * 2;
                    float ox = acc[mt][nt][half*2+0] + bias[col];
                    float oy = acc[mt][nt][half*2+1] + bias[col+1];
                    if (RELU) { ox = fmaxf(ox, 0.f); oy = fmaxf(oy, 0.f); }
                    if (SPLITOUT) {
                        __nv_bfloat16 hx, lx, hy, ly;
                        split2(ox, hx, lx); split2(oy, hy, ly);
                        *(__nv_bfloat162*)(Chi + (size_t)row * N + col) = __nv_bfloat162(hx, hy);
                        *(__nv_bfloat162*)(Clo + (size_t)row * N + col) = __nv_bfloat162(lx, ly);
                    } else {
                        *(float2*)(Cf + (size_t)row * N + col) = make_float2(ox, oy);
                    }
                }
            }
        }
    }
}

// ---------------- weight splitter ------------------------------------------
__global__ void split_weights(const float* __restrict__ w0, const float* __restrict__ w1,
                              const float* __restrict__ w2, const float* __restrict__ w3,
                              const float* __restrict__ w4, const float* __restrict__ w5,
                              const float* __restrict__ w6, const float* __restrict__ w7,
                              __nv_bfloat16* __restrict__ hi, __nv_bfloat16* __restrict__ lo) {
    int i = blockIdx.x * blockDim.x + threadIdx.x;
    if (i >= WTOT) return;
    const float* src; int local;
    if      (i < OFF_SAOUT) { src = w0; local = i; }
    else if (i < OFF_OFFW)  { src = w1; local = i - OFF_SAOUT; }
    else if (i < OFF_AWW)   { src = w2; local = i - OFF_OFFW; }
    else if (i < OFF_VALW)  { src = w3; local = i - OFF_AWW; }
    else if (i < OFF_OUTPW) { src = w4; local = i - OFF_VALW; }
    else if (i < OFF_FFN1)  { src = w5; local = i - OFF_OUTPW; }
    else if (i < OFF_FFN2)  { src = w6; local = i - OFF_FFN1; }
    else                    { src = w7; local = i - OFF_FFN2; }
    __nv_bfloat16 h, l;
    split2(src[local], h, l);
    hi[i] = h; lo[i] = l;
}

// ---------------- add + split: qk = tgt+pos; also split tgt ----------------
__global__ void add_split_kernel(const float* __restrict__ a, const float* __restrict__ b,
                                 __nv_bfloat16* __restrict__ qh, __nv_bfloat16* __restrict__ ql,
                                 __nv_bfloat16* __restrict__ th, __nv_bfloat16* __restrict__ tl,
                                 int n4) {
    int i = blockIdx.x * blockDim.x + threadIdx.x;
    if (i >= n4) return;
    float4 x = ((const float4*)a)[i];
    float4 y = ((const float4*)b)[i];
    float q0 = x.x + y.x, q1 = x.y + y.y, q2 = x.z + y.z, q3 = x.w + y.w;
    __nv_bfloat16 h0,l0,h1,l1,h2,l2,h3,l3;
    split2(q0,h0,l0); split2(q1,h1,l1); split2(q2,h2,l2); split2(q3,h3,l3);
    *(__nv_bfloat162*)(qh + i*4)     = __nv_bfloat162(h0,h1);
    *(__nv_bfloat162*)(qh + i*4 + 2) = __nv_bfloat162(h2,h3);
    *(__nv_bfloat162*)(ql + i*4)     = __nv_bfloat162(l0,l1);
    *(__nv_bfloat162*)(ql + i*4 + 2) = __nv_bfloat162(l2,l3);
    split2(x.x,h0,l0); split2(x.y,h1,l1); split2(x.z,h2,l2); split2(x.w,h3,l3);
    *(__nv_bfloat162*)(th + i*4)     = __nv_bfloat162(h0,h1);
    *(__nv_bfloat162*)(th + i*4 + 2) = __nv_bfloat162(h2,h3);
    *(__nv_bfloat162*)(tl + i*4)     = __nv_bfloat162(l0,l1);
    *(__nv_bfloat162*)(tl + i*4 + 2) = __nv_bfloat162(l2,l3);
}

// ---------------- generic fp32 -> hi/lo splitter (for src) -----------------
__global__ void split_kernel(const float* __restrict__ a,
                             __nv_bfloat16* __restrict__ hi, __nv_bfloat16* __restrict__ lo,
                             int n4) {
    int i = blockIdx.x * blockDim.x + threadIdx.x;
    if (i >= n4) return;
    float4 x = ((const float4*)a)[i];
    __nv_bfloat16 h0,l0,h1,l1,h2,l2,h3,l3;
    split2(x.x,h0,l0); split2(x.y,h1,l1); split2(x.z,h2,l2); split2(x.w,h3,l3);
    *(__nv_bfloat162*)(hi + i*4)     = __nv_bfloat162(h0,h1);
    *(__nv_bfloat162*)(hi + i*4 + 2) = __nv_bfloat162(h2,h3);
    *(__nv_bfloat162*)(lo + i*4)     = __nv_bfloat162(l0,l1);
    *(__nv_bfloat162*)(lo + i*4 + 2) = __nv_bfloat162(l2,l3);
}

// ---------------- flash self-attention, writes split out -------------------
__global__ __launch_bounds__(128)
void attn_kernel(const float* __restrict__ q, const float* __restrict__ k,
                 const float* __restrict__ v,
                 __nv_bfloat16* __restrict__ oh, __nv_bfloat16* __restrict__ ol) {
    const int bh = blockIdx.y;
    const int b = bh / NH, h = bh % NH;
    const int qi = blockIdx.x * 128 + threadIdx.x;
    const bool valid = qi < LQ;
    const float scale = 0.1767766952966369f;

    const float* qb = q + (size_t)b * LQ * DM + h * DH;
    const float* kb = k + (size_t)b * LQ * DM + h * DH;
    const float* vb = v + (size_t)b * LQ * DM + h * DH;

    __shared__ float ks[32][32];
    __shared__ float vs[32][32];

    float qr[32];
    if (valid) {
        #pragma unroll
        for (int c = 0; c < 8; c++) {
            float4 t = *(const float4*)(qb + (size_t)qi * DM + c * 4);
            qr[c*4+0] = t.x; qr[c*4+1] = t.y; qr[c*4+2] = t.z; qr[c*4+3] = t.w;
        }
    }

    float m = -1e30f, l = 0.f;
    float accv[32];
    #pragma unroll
    for (int d = 0; d < 32; d++) accv[d] = 0.f;

    for (int kt = 0; kt < LQ; kt += 32) {
        #pragma unroll
        for (int i = threadIdx.x; i < 256; i += 128) {
            int r = i >> 3, c4 = (i & 7) * 4;
            int kr = kt + r;
            float4 kv = make_float4(0.f,0.f,0.f,0.f), vv = kv;
            if (kr < LQ) {
                kv = *(const float4*)(kb + (size_t)kr * DM + c4);
                vv = *(const float4*)(vb + (size_t)kr * DM + c4);
            }
            *(float4*)&ks[r][c4] = kv;
            *(float4*)&vs[r][c4] = vv;
        }
        __syncthreads();

        if (valid) {
            int nk = LQ - kt; if (nk > 32) nk = 32;
            float s[32];
            float tmax = -1e30f;
            #pragma unroll
            for (int j = 0; j < 32; j++) {
                if (j < nk) {
                    const float4* kr4 = (const float4*)ks[j];
                    float dot = 0.f;
                    #pragma unroll
                    for (int c = 0; c < 8; c++) {
                        float4 kk = kr4[c];
                        dot = fmaf(qr[c*4+0], kk.x, dot);
                        dot = fmaf(qr[c*4+1], kk.y, dot);
                        dot = fmaf(qr[c*4+2], kk.z, dot);
                        dot = fmaf(qr[c*4+3], kk.w, dot);
                    }
                    s[j] = dot * scale;
                    tmax = fmaxf(tmax, s[j]);
                } else s[j] = -1e30f;
            }
            float mnew = fmaxf(m, tmax);
            float corr = __expf(m - mnew);
            l *= corr;
            #pragma unroll
            for (int d = 0; d < 32; d++) accv[d] *= corr;
            #pragma unroll
            for (int j = 0; j < 32; j++) {
                float p = __expf(s[j] - mnew);
                l += p;
                const float4* vr4 = (const float4*)vs[j];
                #pragma unroll
                for (int c = 0; c < 8; c++) {
                    float4 vv = vr4[c];
                    accv[c*4+0] = fmaf(p, vv.x, accv[c*4+0]);
                    accv[c*4+1] = fmaf(p, vv.y, accv[c*4+1]);
                    accv[c*4+2] = fmaf(p, vv.z, accv[c*4+2]);
                    accv[c*4+3] = fmaf(p, vv.w, accv[c*4+3]);
                }
            }
            m = mnew;
        }
        __syncthreads();
    }

    if (valid) {
        float inv = 1.f / l;
        size_t base = ((size_t)b * LQ + qi) * DM + h * DH;
        #pragma unroll
        for (int d = 0; d < 32; d += 2) {
            float v0 = accv[d] * inv, v1 = accv[d+1] * inv;
            __nv_bfloat16 h0,l0,h1,l1;
            split2(v0,h0,l0); split2(v1,h1,l1);
            *(__nv_bfloat162*)(oh + base + d) = __nv_bfloat162(h0,h1);
            *(__nv_bfloat162*)(ol + base + d) = __nv_bfloat162(l0,l1);
        }
    }
}

// ---------------- LayerNorm(x+res) -> fp32 out (+ optional split of out+pos)
__global__ __launch_bounds__(256)
void ln_kernel(const float* __restrict__ x, const float* __restrict__ res,
               const float* __restrict__ g, const float* __restrict__ bta,
               float* __restrict__ out,
               const float* __restrict__ pos,
               __nv_bfloat16* __restrict__ hi, __nv_bfloat16* __restrict__ lo) {
    __shared__ float red[8];
    const int row = blockIdx.x, t = threadIdx.x;
    const size_t idx = (size_t)row * DM + t;
    float v = x[idx] + res[idx];

    float s = v;
    #pragma unroll
    for (int o = 16; o; o >>= 1) s += __shfl_xor_sync(0xffffffffu, s, o);
    if ((t & 31) == 0) red[t >> 5] = s;
    __syncthreads();
    float mean = 0.f;
    #pragma unroll
    for (int i = 0; i < 8; i++) mean += red[i];
    mean *= (1.f / DM);
    __syncthreads();

    float d = v - mean;
    float s2 = d * d;
    #pragma unroll
    for (int o = 16; o; o >>= 1) s2 += __shfl_xor_sync(0xffffffffu, s2, o);
    if ((t & 31) == 0) red[t >> 5] = s2;
    __syncthreads();
    float var = 0.f;
    #pragma unroll
    for (int i = 0; i < 8; i++) var += red[i];
    var *= (1.f / DM);

    float o = d * rsqrtf(var + 1e-5f) * g[t] + bta[t];
    out[idx] = o;
    if (hi) {
        float tq = pos ? o + pos[idx] : o;
        __nv_bfloat16 hh, ll;
        split2(tq, hh, ll);
        hi[idx] = hh; lo[idx] = ll;
    }
}

// ---------------- attention-weight softmax over 16 -------------------------
__global__ void awsm_kernel(float* __restrict__ aw) {
    int i = blockIdx.x * blockDim.x + threadIdx.x;
    if (i >= NQ * NH) return;
    float* p = aw + (size_t)(i / NH) * 128 + (i % NH) * 16;
    float mx = -1e30f;
    #pragma unroll
    for (int j = 0; j < 16; j++) mx = fmaxf(mx, p[j]);
    float sm = 0.f, e[16];
    #pragma unroll
    for (int j = 0; j < 16; j++) { e[j] = __expf(p[j] - mx); sm += e[j]; }
    float inv = 1.f / sm;
    #pragma unroll
    for (int j = 0; j < 16; j++) p[j] = e[j] * inv;
}

// ---------------- MS-deformable sampling, writes split out -----------------
__global__ __launch_bounds__(256)
void deform_kernel(const float* __restrict__ value, const float* __restrict__ off,
                   const float* __restrict__ aw, const float* __restrict__ ref,
                   __nv_bfloat16* __restrict__ oh, __nv_bfloat16* __restrict__ ol) {
    const int qidx = blockIdx.x;
    const int b = qidx / LQ;
    const int h = threadIdx.y, d = threadIdx.x;

    const int starts[4] = {0, 16384, 20480, 21504};
    const int Wi[4]     = {128, 64, 32, 16};

    const float* vb = value + (size_t)b * LEN_IN * DM + h * DH + d;
    const size_t oq = (size_t)qidx;
    float acc = 0.f;

    #pragma unroll
    for (int lvl = 0; lvl < NLV; lvl++) {
        const float W = (float)Wi[lvl];
        const int   Wl = Wi[lvl];
        const int   st = starts[lvl];
        const float rx = ref[(oq * NLV + lvl) * 2 + 0];
        const float ry = ref[(oq * NLV + lvl) * 2 + 1];
        #pragma unroll
        for (int p = 0; p < NPT; p++) {
            const int oidx = ((h * NLV + lvl) * NPT + p) * 2;
            const float ox = off[oq * DM + oidx + 0];
            const float oy = off[oq * DM + oidx + 1];
            const float a  = aw[oq * 128 + h * 16 + lvl * 4 + p];
            const float x = (rx + ox / W) * W - 0.5f;
            const float y = (ry + oy / W) * W - 0.5f;
            const float x0f = floorf(x), y0f = floorf(y);
            const float lx = x - x0f, ly = y - y0f;
            const int x0 = (int)x0f, y0 = (int)y0f;

            const float w00 = (1.f - ly) * (1.f - lx);
            const float w01 = (1.f - ly) * lx;
            const float w10 = ly * (1.f - lx);
            const float w11 = ly * lx;

            const bool xv0 = (x0 >= 0) & (x0 < Wl);
            const bool xv1 = (x0 + 1 >= 0) & (x0 + 1 < Wl);
            const bool yv0 = (y0 >= 0) & (y0 < Wl);
            const bool yv1 = (y0 + 1 >= 0) & (y0 + 1 < Wl);

            if (yv0 & xv0) acc = fmaf(a * w00, vb[(size_t)(st + y0 * Wl + x0) * DM], acc);
            if (yv0 & xv1) acc = fmaf(a * w01, vb[(size_t)(st + y0 * Wl + x0 + 1) * DM], acc);
            if (yv1 & xv0) acc = fmaf(a * w10, vb[(size_t)(st + (y0 + 1) * Wl + x0) * DM], acc);
            if (yv1 & xv1) acc = fmaf(a * w11, vb[(size_t)(st + (y0 + 1) * Wl + x0 + 1) * DM], acc);
        }
    }
    __nv_bfloat16 hh, ll;
    split2(acc, hh, ll);
    oh[oq * DM + h * DH + d] = hh;
    ol[oq * DM + h * DH + d] = ll;
}

// ---------------- host-side orchestration ----------------------------------
static inline void gemm_bf(const __nv_bfloat16* Ah, const __nv_bfloat16* Al,
                           const __nv_bfloat16* Bh, const __nv_bfloat16* Bl,
                           const float* bias, float* Cf,
                           __nv_bfloat16* Chi, __nv_bfloat16* Clo,
                           int M, int N, int K, bool relu_split) {
    dim3 grid(N / 128, (M + 127) / 128);
    if (relu_split)
        tc_gemm_bf<true, true><<<grid, 256, TCG_SMEM>>>(Ah, Al, Bh, Bl, bias, Cf, Chi, Clo, M, N, K);
    else
        tc_gemm_bf<false, false><<<grid, 256, TCG_SMEM>>>(Ah, Al, Bh, Bl, bias, Cf, Chi, Clo, M, N, K);
}

extern "C" void kernel_launch(void* const* d_in, const int* in_sizes, int n_in,
                              void* d_out, int out_size) {
    (void)in_sizes; (void)n_in; (void)out_size;
    const float* tgt       = (const float*)d_in[0];
    const float* query_pos = (const float*)d_in[1];
    const float* refpts    = (const float*)d_in[2];
    const float* src       = (const float*)d_in[3];
    const float* sa_in_w   = (const float*)d_in[6];
    const float* sa_in_b   = (const float*)d_in[7];
    const float* sa_out_w  = (const float*)d_in[8];
    const float* sa_out_b  = (const float*)d_in[9];
    const float* norm2_g   = (const float*)d_in[10];
    const float* norm2_b   = (const float*)d_in[11];
    const float* off_w     = (const float*)d_in[12];
    const float* off_b     = (const float*)d_in[13];
    const float* aw_w      = (const float*)d_in[14];
    const float* aw_b      = (const float*)d_in[15];
    const float* val_w     = (const float*)d_in[16];
    const float* val_b     = (const float*)d_in[17];
    const float* outp_w    = (const float*)d_in[18];
    const float* outp_b    = (const float*)d_in[19];
    const float* norm1_g   = (const float*)d_in[20];
    const float* norm1_b   = (const float*)d_in[21];
    const float* ffn_w1    = (const float*)d_in[22];
    const float* ffn_b1    = (const float*)d_in[23];
    const float* ffn_w2    = (const float*)d_in[24];
    const float* ffn_b2    = (const float*)d_in[25];
    const float* norm3_g   = (const float*)d_in[26];
    const float* norm3_b   = (const float*)d_in[27];
    float* out = (float*)d_out;

    cudaFuncSetAttribute(tc_gemm_bf<false,false>, cudaFuncAttributeMaxDynamicSharedMemorySize, TCG_SMEM);
    cudaFuncSetAttribute(tc_gemm_bf<true,true>,   cudaFuncAttributeMaxDynamicSharedMemorySize, TCG_SMEM);

    void* p;
    #define SYMF(name) cudaGetSymbolAddress(&p, name); float* name##_p = (float*)p;
    #define SYMB(name) cudaGetSymbolAddress(&p, name); __nv_bfloat16* name##_p = (__nv_bfloat16*)p;
    SYMF(g_q) SYMF(g_k) SYMF(g_v) SYMF(g_proj) SYMF(g_tgt2) SYMF(g_tgt3)
    SYMF(g_off) SYMF(g_aw) SYMF(g_value)
    SYMB(g_qk_h) SYMB(g_qk_l) SYMB(g_tgt_h) SYMB(g_tgt_l)
    SYMB(g_att_h) SYMB(g_att_l) SYMB(g_query_h) SYMB(g_query_l)
    SYMB(g_tgt3_h) SYMB(g_tgt3_l) SYMB(g_ca_h) SYMB(g_ca_l)
    SYMB(g_ffn_h) SYMB(g_ffn_l) SYMB(g_src_h) SYMB(g_src_l)
    SYMB(g_wh) SYMB(g_wl)
    #undef SYMF
    #undef SYMB

    // 0) weight + input splits
    split_weights<<<(WTOT + 255)/256, 256>>>(sa_in_w, sa_out_w, off_w, aw_w, val_w,
                                             outp_w, ffn_w1, ffn_w2, g_wh_p, g_wl_p);
    const int n4 = NQ * DM / 4;
    add_split_kernel<<<(n4 + 255)/256, 256>>>(tgt, query_pos, g_qk_h_p, g_qk_l_p,
                                              g_tgt_h_p, g_tgt_l_p, n4);
    const int ns4 = (int)((size_t)NSRC * DM / 4);
    split_kernel<<<(ns4 + 255)/256, 256>>>(src, g_src_h_p, g_src_l_p, ns4);

    // 1) self-attn projections
    gemm_bf(g_qk_h_p, g_qk_l_p, g_wh_p + OFF_SAIN,          g_wl_p + OFF_SAIN,          sa_in_b,       g_q_p, 0, 0, NQ, DM, DM, false);
    gemm_bf(g_qk_h_p, g_qk_l_p, g_wh_p + OFF_SAIN + 65536,  g_wl_p + OFF_SAIN + 65536,  sa_in_b + DM,  g_k_p, 0, 0, NQ, DM, DM, false);
    gemm_bf(g_tgt_h_p, g_tgt_l_p, g_wh_p + OFF_SAIN + 131072, g_wl_p + OFF_SAIN + 131072, sa_in_b + 2*DM, g_v_p, 0, 0, NQ, DM, DM, false);
    attn_kernel<<<dim3((LQ + 127)/128, NB * NH), 128>>>(g_q_p, g_k_p, g_v_p, g_att_h_p, g_att_l_p);
    gemm_bf(g_att_h_p, g_att_l_p, g_wh_p + OFF_SAOUT, g_wl_p + OFF_SAOUT, sa_out_b, g_proj_p, 0, 0, NQ, DM, DM, false);
    ln_kernel<<<NQ, DM>>>(tgt, g_proj_p, norm2_g, norm2_b, g_tgt2_p, query_pos, g_query_h_p, g_query_l_p);

    // 2) cross-attn
    gemm_bf(g_src_h_p, g_src_l_p, g_wh_p + OFF_VALW, g_wl_p + OFF_VALW, val_b, g_value_p, 0, 0, NSRC, DM, DM, false);
    gemm_bf(g_query_h_p, g_query_l_p, g_wh_p + OFF_OFFW, g_wl_p + OFF_OFFW, off_b, g_off_p, 0, 0, NQ, DM, DM, false);
    gemm_bf(g_query_h_p, g_query_l_p, g_wh_p + OFF_AWW,  g_wl_p + OFF_AWW,  aw_b,  g_aw_p,  0, 0, NQ, 128, DM, false);
    awsm_kernel<<<(NQ * NH + 255)/256, 256>>>(g_aw_p);
    deform_kernel<<<NQ, dim3(32, 8)>>>(g_value_p, g_off_p, g_aw_p, refpts, g_ca_h_p, g_ca_l_p);
    gemm_bf(g_ca_h_p, g_ca_l_p, g_wh_p + OFF_OUTPW, g_wl_p + OFF_OUTPW, outp_b, g_proj_p, 0, 0, NQ, DM, DM, false);
    ln_kernel<<<NQ, DM>>>(g_tgt2_p, g_proj_p, norm1_g, norm1_b, g_tgt3_p, nullptr, g_tgt3_h_p, g_tgt3_l_p);

    // 3) FFN
    gemm_bf(g_tgt3_h_p, g_tgt3_l_p, g_wh_p + OFF_FFN1, g_wl_p + OFF_FFN1, ffn_b1, 0, g_ffn_h_p, g_ffn_l_p, NQ, DFFN, DM, true);
    gemm_bf(g_ffn_h_p, g_ffn_l_p, g_wh_p + OFF_FFN2, g_wl_p + OFF_FFN2, ffn_b2, g_proj_p, 0, 0, NQ, DM, DFFN, false);
    ln_kernel<<<NQ, DM>>>(g_tgt3_p, g_proj_p, norm3_g, norm3_b, out, nullptr, nullptr, nullptr);
}